// round 7
// baseline (speedup 1.0000x reference)
#include <cuda_runtime.h>
#include <math.h>
#include <stdint.h>

// ---------------- problem constants ----------------
#define B_    4
#define S_    4096
#define HID_  1024
#define NH_   16
#define D_    64
#define WIN_  512
#define CHUNK_ 128
#define CPW_  4
#define NW_   8
#define NC_   32
#define SCALE_ 0.125f
#define M_TOT (B_*S_)        // 16384 rows

// ---------------- scratch (device globals; no allocation allowed) ----------------
__device__ float g_q[B_*NH_*S_*D_];     // (B,H,S,D) rope'd q
__device__ float g_k[B_*NH_*S_*D_];     // (B,H,S,D) rope'd k
__device__ float g_v[B_*NH_*S_*D_];     // (B,H,S,D)
__device__ float g_att[B_*S_*HID_];     // (B,S,HID) attention output pre-Wo
__device__ float g_rfa_k[B_*NH_*NC_*D_];
__device__ float g_rfa_v[B_*NH_*NC_*D_];

// ---------------- packed fp32x2 helpers (sm_103a FFMA2 path) ----------------
__device__ __forceinline__ unsigned long long pack2(float lo, float hi) {
    unsigned long long r;
    asm("mov.b64 %0, {%1, %2};" : "=l"(r) : "f"(lo), "f"(hi));
    return r;
}
__device__ __forceinline__ void unpack2(unsigned long long v, float& lo, float& hi) {
    asm("mov.b64 {%0, %1}, %2;" : "=f"(lo), "=f"(hi) : "l"(v));
}
__device__ __forceinline__ unsigned long long fma2(unsigned long long a,
                                                   unsigned long long b,
                                                   unsigned long long c) {
    unsigned long long d;
    asm("fma.rn.f32x2 %0, %1, %2, %3;" : "=l"(d) : "l"(a), "l"(b), "l"(c));
    return d;
}
__device__ __forceinline__ unsigned long long add2(unsigned long long a,
                                                   unsigned long long b) {
    unsigned long long d;
    asm("add.rn.f32x2 %0, %1, %2;" : "=l"(d) : "l"(a), "l"(b));
    return d;
}
__device__ __forceinline__ unsigned long long mul2(unsigned long long a,
                                                   unsigned long long b) {
    unsigned long long d;
    asm("mul.rn.f32x2 %0, %1, %2;" : "=l"(d) : "l"(a), "l"(b));
    return d;
}

// =======================================================================
// 3xTF32 tensor-core GEMM core: C[m][n] = sum_k X[m][k] * W[n][k]  (X @ W^T)
// M=16384, N=1024, K=1024.
// Block tile 128x128, BK=16, 256 threads = 8 warps (4m x 2n), warp tile 32x64.
// hi/lo split done ONCE at smem staging; smem holds float2{hi,lo} (LDS.64).
// XOR swizzle p = col ^ (((row>>2)&3)<<2) -> conflict-free stores AND loads
// (verified per 16-lane phase for 8B accesses).
// mma.sync.m16n8k8.tf32: acc += Ahi*Bhi + Ahi*Blo + Alo*Bhi.
// =======================================================================
__device__ __forceinline__ uint32_t f32_to_tf32(float x) {
    uint32_t r;
    asm("cvt.rna.tf32.f32 %0, %1;" : "=r"(r) : "f"(x));
    return r;
}
__device__ __forceinline__ float2 split_tf32(float x) {
    uint32_t hb = f32_to_tf32(x);
    float h = __uint_as_float(hb);
    uint32_t lb = f32_to_tf32(x - h);
    return make_float2(h, __uint_as_float(lb));
}
__device__ __forceinline__ void mma_tf32(float c[4], const uint32_t a[4],
                                         uint32_t b0, uint32_t b1) {
    asm volatile(
        "mma.sync.aligned.m16n8k8.row.col.f32.tf32.tf32.f32 "
        "{%0,%1,%2,%3}, {%4,%5,%6,%7}, {%8,%9}, {%0,%1,%2,%3};"
        : "+f"(c[0]), "+f"(c[1]), "+f"(c[2]), "+f"(c[3])
        : "r"(a[0]), "r"(a[1]), "r"(a[2]), "r"(a[3]), "r"(b0), "r"(b1));
}

#define LD2 132   // float2 row stride (8 banks/row)
#define SWZ(row, col) ((col) ^ ((((row) >> 2) & 3) << 2))

struct GemmCtx {
    int tid, lane, warp, gid, tig, wm, wn, bm, bn;
};

__device__ __forceinline__ void gemm_mainloop(
    const float* __restrict__ X, const float* __restrict__ W,
    const GemmCtx& g, float c[2][8][4],
    float2 (*As2)[LD2], float2 (*Bs2)[LD2])
{
    #pragma unroll
    for (int mt = 0; mt < 2; mt++)
        #pragma unroll
        for (int nt = 0; nt < 8; nt++)
            #pragma unroll
            for (int r = 0; r < 4; r++) c[mt][nt][r] = 0.f;

    const int ml0 = g.tid >> 2, kl0 = (g.tid & 3) << 2;
    const int ml1 = ml0 + 64;

    const float* Xr0 = &X[(size_t)(g.bm + ml0) * HID_ + kl0];
    const float* Xr1 = &X[(size_t)(g.bm + ml1) * HID_ + kl0];
    const float* Wr0 = &W[(size_t)(g.bn + ml0) * HID_ + kl0];
    const float* Wr1 = &W[(size_t)(g.bn + ml1) * HID_ + kl0];

    float4 ra0 = *(const float4*)&Xr0[0];
    float4 ra1 = *(const float4*)&Xr1[0];
    float4 rb0 = *(const float4*)&Wr0[0];
    float4 rb1 = *(const float4*)&Wr1[0];

    for (int k0 = 0; k0 < HID_; k0 += 16) {
        As2[kl0 + 0][SWZ(kl0 + 0, ml0)] = split_tf32(ra0.x);
        As2[kl0 + 1][SWZ(kl0 + 1, ml0)] = split_tf32(ra0.y);
        As2[kl0 + 2][SWZ(kl0 + 2, ml0)] = split_tf32(ra0.z);
        As2[kl0 + 3][SWZ(kl0 + 3, ml0)] = split_tf32(ra0.w);
        As2[kl0 + 0][SWZ(kl0 + 0, ml1)] = split_tf32(ra1.x);
        As2[kl0 + 1][SWZ(kl0 + 1, ml1)] = split_tf32(ra1.y);
        As2[kl0 + 2][SWZ(kl0 + 2, ml1)] = split_tf32(ra1.z);
        As2[kl0 + 3][SWZ(kl0 + 3, ml1)] = split_tf32(ra1.w);
        Bs2[kl0 + 0][SWZ(kl0 + 0, ml0)] = split_tf32(rb0.x);
        Bs2[kl0 + 1][SWZ(kl0 + 1, ml0)] = split_tf32(rb0.y);
        Bs2[kl0 + 2][SWZ(kl0 + 2, ml0)] = split_tf32(rb0.z);
        Bs2[kl0 + 3][SWZ(kl0 + 3, ml0)] = split_tf32(rb0.w);
        Bs2[kl0 + 0][SWZ(kl0 + 0, ml1)] = split_tf32(rb1.x);
        Bs2[kl0 + 1][SWZ(kl0 + 1, ml1)] = split_tf32(rb1.y);
        Bs2[kl0 + 2][SWZ(kl0 + 2, ml1)] = split_tf32(rb1.z);
        Bs2[kl0 + 3][SWZ(kl0 + 3, ml1)] = split_tf32(rb1.w);
        __syncthreads();

        if (k0 + 16 < HID_) {
            ra0 = *(const float4*)&Xr0[k0 + 16];
            ra1 = *(const float4*)&Xr1[k0 + 16];
            rb0 = *(const float4*)&Wr0[k0 + 16];
            rb1 = *(const float4*)&Wr1[k0 + 16];
        }

        #pragma unroll
        for (int ks = 0; ks < 2; ks++) {
            const int kb = ks * 8;
            uint32_t ah[2][4], al[2][4];
            #pragma unroll
            for (int mt = 0; mt < 2; mt++) {
                int m0 = g.wm * 32 + mt * 16;
                float2 v0 = As2[kb + g.tig    ][SWZ(kb + g.tig,     m0 + g.gid)];
                float2 v1 = As2[kb + g.tig    ][SWZ(kb + g.tig,     m0 + g.gid + 8)];
                float2 v2 = As2[kb + g.tig + 4][SWZ(kb + g.tig + 4, m0 + g.gid)];
                float2 v3 = As2[kb + g.tig + 4][SWZ(kb + g.tig + 4, m0 + g.gid + 8)];
                ah[mt][0] = __float_as_uint(v0.x); al[mt][0] = __float_as_uint(v0.y);
                ah[mt][1] = __float_as_uint(v1.x); al[mt][1] = __float_as_uint(v1.y);
                ah[mt][2] = __float_as_uint(v2.x); al[mt][2] = __float_as_uint(v2.y);
                ah[mt][3] = __float_as_uint(v3.x); al[mt][3] = __float_as_uint(v3.y);
            }
            #pragma unroll
            for (int nt = 0; nt < 8; nt++) {
                int n0 = g.wn * 64 + nt * 8;
                float2 w0 = Bs2[kb + g.tig    ][SWZ(kb + g.tig,     n0 + g.gid)];
                float2 w1 = Bs2[kb + g.tig + 4][SWZ(kb + g.tig + 4, n0 + g.gid)];
                uint32_t bh0 = __float_as_uint(w0.x), bl0 = __float_as_uint(w0.y);
                uint32_t bh1 = __float_as_uint(w1.x), bl1 = __float_as_uint(w1.y);
                #pragma unroll
                for (int mt = 0; mt < 2; mt++) {
                    mma_tf32(c[mt][nt], ah[mt], bh0, bh1);
                    mma_tf32(c[mt][nt], ah[mt], bl0, bl1);
                    mma_tf32(c[mt][nt], al[mt], bh0, bh1);
                }
            }
        }
        __syncthreads();
    }
}

__device__ __forceinline__ GemmCtx make_ctx(int bx, int by) {
    GemmCtx g;
    g.tid  = threadIdx.x;
    g.lane = g.tid & 31;
    g.warp = g.tid >> 5;
    g.gid  = g.lane >> 2;
    g.tig  = g.lane & 3;
    g.wm   = g.warp & 3;
    g.wn   = g.warp >> 2;
    g.bm   = by * 128;
    g.bn   = bx * 128;
    return g;
}

// ---- fused QKV projection: blockIdx.z selects {q(+rope), k(+rope), v} ----
__global__ __launch_bounds__(256)
void tgemm_qkv(const float* __restrict__ X,
               const float* __restrict__ Wq, const float* __restrict__ Wk,
               const float* __restrict__ Wv,
               const float* __restrict__ cosT, const float* __restrict__ sinT)
{
    __shared__ __align__(16) float2 As2[16][LD2];
    __shared__ __align__(16) float2 Bs2[16][LD2];
    GemmCtx g = make_ctx(blockIdx.x, blockIdx.y);
    const int bz = blockIdx.z;
    const float* W = (bz == 0) ? Wq : (bz == 1) ? Wk : Wv;
    float* Cout    = (bz == 0) ? g_q : (bz == 1) ? g_k : g_v;

    float c[2][8][4];
    gemm_mainloop(X, W, g, c, As2, Bs2);

    int h = (g.bn + g.wn * 64) >> 6;
    if (bz < 2) {
        // scatter into (B,H,S,D) with fused RoPE; thread holds (dd, dd+32) as (nt, nt+4)
        #pragma unroll
        for (int mt = 0; mt < 2; mt++) {
            #pragma unroll
            for (int half = 0; half < 2; half++) {
                int m  = g.bm + g.wm * 32 + mt * 16 + g.gid + half * 8;
                int b_ = m / S_, s_ = m % S_;
                const float* cr = cosT + (size_t)s_ * D_;
                const float* sr = sinT + (size_t)s_ * D_;
                float* dst = &Cout[(((size_t)(b_ * NH_ + h)) * S_ + s_) * D_];
                #pragma unroll
                for (int nt = 0; nt < 4; nt++) {
                    int dd = nt * 8 + 2 * g.tig;
                    float o1[2], o2[2];
                    #pragma unroll
                    for (int j = 0; j < 2; j++) {
                        float x1 = c[mt][nt    ][half * 2 + j];
                        float x2 = c[mt][nt + 4][half * 2 + j];
                        o1[j] = x1 * cr[dd + j]      - x2 * sr[dd + j];
                        o2[j] = x2 * cr[dd + 32 + j] + x1 * sr[dd + 32 + j];
                    }
                    *(float2*)&dst[dd]      = make_float2(o1[0], o1[1]);
                    *(float2*)&dst[dd + 32] = make_float2(o2[0], o2[1]);
                }
            }
        }
    } else {
        // plain scatter into (B,H,S,D)
        #pragma unroll
        for (int mt = 0; mt < 2; mt++) {
            #pragma unroll
            for (int nt = 0; nt < 8; nt++) {
                int dd = nt * 8 + 2 * g.tig;
                #pragma unroll
                for (int half = 0; half < 2; half++) {
                    int m  = g.bm + g.wm * 32 + mt * 16 + g.gid + half * 8;
                    int b_ = m / S_, s_ = m % S_;
                    *(float2*)&Cout[(((size_t)(b_ * NH_ + h)) * S_ + s_) * D_ + dd] =
                        make_float2(c[mt][nt][half * 2], c[mt][nt][half * 2 + 1]);
                }
            }
        }
    }
}

// ---- output projection: row-major result into d_out ----
__global__ __launch_bounds__(256)
void tgemm_out(const float* __restrict__ X, const float* __restrict__ W,
               float* __restrict__ Cout)
{
    __shared__ __align__(16) float2 As2[16][LD2];
    __shared__ __align__(16) float2 Bs2[16][LD2];
    GemmCtx g = make_ctx(blockIdx.x, blockIdx.y);

    float c[2][8][4];
    gemm_mainloop(X, W, g, c, As2, Bs2);

    #pragma unroll
    for (int mt = 0; mt < 2; mt++) {
        #pragma unroll
        for (int nt = 0; nt < 8; nt++) {
            int n0 = g.bn + g.wn * 64 + nt * 8 + 2 * g.tig;
            #pragma unroll
            for (int half = 0; half < 2; half++) {
                int m = g.bm + g.wm * 32 + mt * 16 + g.gid + half * 8;
                *(float2*)&Cout[(size_t)m * HID_ + n0] =
                    make_float2(c[mt][nt][half * 2], c[mt][nt][half * 2 + 1]);
            }
        }
    }
}

// =======================================================================
// RFA chunk summaries: block per (b,h,c), 128 threads (one per key in chunk).
// =======================================================================
__global__ __launch_bounds__(128)
void rfa_kernel(const float* __restrict__ mu, const float* __restrict__ phi)
{
    int bid = blockIdx.x;          // B*NH*NC
    int c  = bid % NC_;
    int bh = bid / NC_;
    int h  = bh % NH_;
    const float* kc = g_k + ((size_t)bh * S_ + (size_t)c * CHUNK_) * D_;
    const float* vc = g_v + ((size_t)bh * S_ + (size_t)c * CHUNK_) * D_;

    __shared__ float sb[CHUNK_], sg[CHUNK_];
    int j = threadIdx.x;

    float dm = 0.f, dp = 0.f, nn = 0.f;
    const float4* krow = (const float4*)(kc + (size_t)j * D_);
    const float4* mu4  = (const float4*)(mu + h * D_);
    const float4* ph4  = (const float4*)(phi + h * D_);
    #pragma unroll
    for (int d4 = 0; d4 < 16; d4++) {
        float4 kv = krow[d4], m4 = mu4[d4], p4 = ph4[d4];
        dm += kv.x * m4.x + kv.y * m4.y + kv.z * m4.z + kv.w * m4.w;
        dp += kv.x * p4.x + kv.y * p4.y + kv.z * p4.z + kv.w * p4.w;
        nn += kv.x * kv.x + kv.y * kv.y + kv.z * kv.z + kv.w * kv.w;
    }
    float lb = SCALE_ * dm - SCALE_ * 0.5f * nn;
    float lg = SCALE_ * dp - SCALE_ * 0.5f * nn;
    sb[j] = lb; sg[j] = lg;
    __syncthreads();

    float mb = -INFINITY, mg = -INFINITY;
    for (int t = 0; t < CHUNK_; t++) { mb = fmaxf(mb, sb[t]); mg = fmaxf(mg, sg[t]); }
    float eb = __expf(lb - mb), eg = __expf(lg - mg);
    __syncthreads();
    sb[j] = eb; sg[j] = eg;
    __syncthreads();
    float ssb = 0.f, ssg = 0.f;
    for (int t = 0; t < CHUNK_; t++) { ssb += sb[t]; ssg += sg[t]; }
    float beta  = eb / ssb;
    float gamma = eg / ssg;
    __syncthreads();
    sb[j] = beta; sg[j] = gamma;
    __syncthreads();

    if (threadIdx.x < 64) {
        int d = threadIdx.x;
        float a = 0.f;
        for (int t = 0; t < CHUNK_; t++) a += sb[t] * kc[(size_t)t * D_ + d];
        g_rfa_k[((size_t)bh * NC_ + c) * D_ + d] = a;
    } else {
        int d = threadIdx.x - 64;
        float a = 0.f;
        for (int t = 0; t < CHUNK_; t++) a += sg[t] * vc[(size_t)t * D_ + d];
        g_rfa_v[((size_t)bh * NC_ + c) * D_ + d] = a;
    }
}

// =======================================================================
// Attention: block = (b,h,w, query-tile of 128). One query row per thread,
// streaming softmax over (causal window keys) ++ (allowed RFA chunks).
// Inner loops use packed fp32x2 (FFMA2) — 2 fp32 FMA per instruction.
// =======================================================================
__global__ __launch_bounds__(128, 2)
void attn_kernel()
{
    int bid = blockIdx.x;               // B*NH*NW*4
    int qt = bid & 3;
    int w  = (bid >> 2) & 7;
    int bh = bid >> 5;                  // b*NH + h
    int h  = bh % NH_;
    int b_ = bh / NH_;

    const float* qbase = g_q + ((size_t)bh * S_ + (size_t)w * WIN_ + (size_t)qt * 128) * D_;
    const float* kbase = g_k + ((size_t)bh * S_ + (size_t)w * WIN_) * D_;
    const float* vbase = g_v + ((size_t)bh * S_ + (size_t)w * WIN_) * D_;

    const int tid = threadIdx.x;

    // load q, fold scale, pack into fp32x2 pairs
    unsigned long long q2[32];
    {
        const float4* qr = (const float4*)(qbase + (size_t)tid * D_);
        #pragma unroll
        for (int i = 0; i < 16; i++) {
            float4 v = qr[i];
            q2[2*i]   = pack2(v.x * SCALE_, v.y * SCALE_);
            q2[2*i+1] = pack2(v.z * SCALE_, v.w * SCALE_);
        }
    }
    unsigned long long acc2[32];
    #pragma unroll
    for (int i = 0; i < 32; i++) acc2[i] = 0ULL;   // {0.0f, 0.0f}
    float m = -INFINITY, l = 0.f;

    __shared__ __align__(16) float ks[64][D_];
    __shared__ __align__(16) float vs[64][D_];

    const int jmax_local = qt * 128 + tid;       // inclusive causal limit
    const int ntiles = qt * 2 + 2;

    for (int t = 0; t < ntiles; t++) {
        __syncthreads();
        #pragma unroll
        for (int i = 0; i < 8; i++) {
            int f = tid + i * 128;
            int row = f >> 4, col = (f & 15) << 2;
            *(float4*)&ks[row][col] = *(const float4*)&kbase[(size_t)(t * 64 + row) * D_ + col];
            *(float4*)&vs[row][col] = *(const float4*)&vbase[(size_t)(t * 64 + row) * D_ + col];
        }
        __syncthreads();

        int jend = jmax_local - t * 64 + 1;
        if (jend > 64) jend = 64;
        for (int jj = 0; jj < jend; jj++) {
            const ulonglong2* kr = (const ulonglong2*)ks[jj];
            unsigned long long s0 = 0ULL, s1 = 0ULL, s2 = 0ULL, s3 = 0ULL;
            #pragma unroll
            for (int i = 0; i < 8; i++) {
                ulonglong2 ka = kr[2*i];
                ulonglong2 kb = kr[2*i+1];
                s0 = fma2(q2[4*i],   ka.x, s0);
                s1 = fma2(q2[4*i+1], ka.y, s1);
                s2 = fma2(q2[4*i+2], kb.x, s2);
                s3 = fma2(q2[4*i+3], kb.y, s3);
            }
            s0 = add2(s0, s1);
            s2 = add2(s2, s3);
            s0 = add2(s0, s2);
            float slo, shi;
            unpack2(s0, slo, shi);
            float s = slo + shi;

            if (s > m) {
                float corr = __expf(m - s);
                unsigned long long c2 = pack2(corr, corr);
                #pragma unroll
                for (int i = 0; i < 32; i++) acc2[i] = mul2(acc2[i], c2);
                l *= corr;
                m = s;
            }
            float p = __expf(s - m);
            l += p;
            unsigned long long p2 = pack2(p, p);
            const ulonglong2* vr = (const ulonglong2*)vs[jj];
            #pragma unroll
            for (int i = 0; i < 16; i++) {
                ulonglong2 vv = vr[i];
                acc2[2*i]   = fma2(p2, vv.x, acc2[2*i]);
                acc2[2*i+1] = fma2(p2, vv.y, acc2[2*i+1]);
            }
        }
    }

    // ---- chunk-RFA part: chunks c < w*CPW ----
    const int ncn = w * CPW_;
    __syncthreads();
    for (int f = tid; f < ncn * 16; f += 128) {
        int row = f >> 4, col = (f & 15) << 2;
        *(float4*)&ks[row][col] = *(const float4*)&g_rfa_k[((size_t)bh * NC_ + row) * D_ + col];
        *(float4*)&vs[row][col] = *(const float4*)&g_rfa_v[((size_t)bh * NC_ + row) * D_ + col];
    }
    __syncthreads();
    for (int c = 0; c < ncn; c++) {
        const ulonglong2* kr = (const ulonglong2*)ks[c];
        unsigned long long s0 = 0ULL, s1 = 0ULL, s2 = 0ULL, s3 = 0ULL;
        #pragma unroll
        for (int i = 0; i < 8; i++) {
            ulonglong2 ka = kr[2*i];
            ulonglong2 kb = kr[2*i+1];
            s0 = fma2(q2[4*i],   ka.x, s0);
            s1 = fma2(q2[4*i+1], ka.y, s1);
            s2 = fma2(q2[4*i+2], kb.x, s2);
            s3 = fma2(q2[4*i+3], kb.y, s3);
        }
        s0 = add2(s0, s1);
        s2 = add2(s2, s3);
        s0 = add2(s0, s2);
        float slo, shi;
        unpack2(s0, slo, shi);
        float s = slo + shi;

        if (s > m) {
            float corr = __expf(m - s);
            unsigned long long c2 = pack2(corr, corr);
            #pragma unroll
            for (int i = 0; i < 32; i++) acc2[i] = mul2(acc2[i], c2);
            l *= corr;
            m = s;
        }
        float p = __expf(s - m);
        l += p;
        unsigned long long p2 = pack2(p, p);
        const ulonglong2* vr = (const ulonglong2*)vs[c];
        #pragma unroll
        for (int i = 0; i < 16; i++) {
            ulonglong2 vv = vr[i];
            acc2[2*i]   = fma2(p2, vv.x, acc2[2*i]);
            acc2[2*i+1] = fma2(p2, vv.y, acc2[2*i+1]);
        }
    }

    float inv = 1.0f / l;
    unsigned long long inv2 = pack2(inv, inv);
    int sg_ = w * WIN_ + qt * 128 + tid;
    float* out = g_att + ((size_t)b_ * S_ + sg_) * HID_ + (size_t)h * D_;
    #pragma unroll
    for (int i = 0; i < 16; i++) {
        unsigned long long t0 = mul2(acc2[2*i],   inv2);
        unsigned long long t1 = mul2(acc2[2*i+1], inv2);
        float a, b, cc, d;
        unpack2(t0, a, b);
        unpack2(t1, cc, d);
        *(float4*)&out[i * 4] = make_float4(a, b, cc, d);
    }
}

// =======================================================================
// launch
// =======================================================================
extern "C" void kernel_launch(void* const* d_in, const int* in_sizes, int n_in,
                              void* d_out, int out_size)
{
    const float* X    = (const float*)d_in[0];   // hidden_states (B,S,HID)
    const float* Wq   = (const float*)d_in[1];
    const float* Wk   = (const float*)d_in[2];
    const float* Wv   = (const float*)d_in[3];
    const float* Wo   = (const float*)d_in[4];
    const float* mu   = (const float*)d_in[5];   // (1,NH,1,1,D)
    const float* phi  = (const float*)d_in[6];
    const float* cosT = (const float*)d_in[7];   // (1,1,S,D)
    const float* sinT = (const float*)d_in[8];
    float* out = (float*)d_out;

    float* att_p;
    cudaGetSymbolAddress((void**)&att_p, g_att);

    // fused q/k/v projections (+RoPE for q,k) -> (B,H,S,D)
    dim3 qkv_grid(HID_ / 128, M_TOT / 128, 3);   // (8, 128, 3)
    tgemm_qkv<<<qkv_grid, 256>>>(X, Wq, Wk, Wv, cosT, sinT);

    // RFA chunk summaries
    rfa_kernel<<<B_ * NH_ * NC_, 128>>>(mu, phi);

    // attention
    attn_kernel<<<B_ * NH_ * NW_ * 4, 128>>>();

    // output projection -> d_out
    dim3 ogrid(HID_ / 128, M_TOT / 128);         // (8, 128)
    tgemm_out<<<ogrid, 256>>>(att_p, Wo, out);
}

// round 13
// speedup vs baseline: 1.2185x; 1.2185x over previous
#include <cuda_runtime.h>
#include <math.h>
#include <stdint.h>

// ---------------- problem constants ----------------
#define B_    4
#define S_    4096
#define HID_  1024
#define NH_   16
#define D_    64
#define WIN_  512
#define CHUNK_ 128
#define CPW_  4
#define NW_   8
#define NC_   32
#define SCALE_ 0.125f
#define M_TOT (B_*S_)        // 16384 rows

// ---------------- scratch (device globals; no allocation allowed) ----------------
__device__ float g_q[B_*NH_*S_*D_];     // (B,H,S,D) rope'd q
__device__ float g_k[B_*NH_*S_*D_];     // (B,H,S,D) rope'd k
__device__ float g_v[B_*NH_*S_*D_];     // (B,H,S,D)
__device__ float g_att[B_*S_*HID_];     // (B,S,HID) attention output pre-Wo
__device__ float g_rfa_k[B_*NH_*NC_*D_];
__device__ float g_rfa_v[B_*NH_*NC_*D_];

// ---------------- packed fp32x2 helpers (sm_103a FFMA2 path) ----------------
__device__ __forceinline__ unsigned long long pack2(float lo, float hi) {
    unsigned long long r;
    asm("mov.b64 %0, {%1, %2};" : "=l"(r) : "f"(lo), "f"(hi));
    return r;
}
__device__ __forceinline__ void unpack2(unsigned long long v, float& lo, float& hi) {
    asm("mov.b64 {%0, %1}, %2;" : "=f"(lo), "=f"(hi) : "l"(v));
}
__device__ __forceinline__ unsigned long long fma2(unsigned long long a,
                                                   unsigned long long b,
                                                   unsigned long long c) {
    unsigned long long d;
    asm("fma.rn.f32x2 %0, %1, %2, %3;" : "=l"(d) : "l"(a), "l"(b), "l"(c));
    return d;
}
__device__ __forceinline__ unsigned long long add2(unsigned long long a,
                                                   unsigned long long b) {
    unsigned long long d;
    asm("add.rn.f32x2 %0, %1, %2;" : "=l"(d) : "l"(a), "l"(b));
    return d;
}
__device__ __forceinline__ unsigned long long mul2(unsigned long long a,
                                                   unsigned long long b) {
    unsigned long long d;
    asm("mul.rn.f32x2 %0, %1, %2;" : "=l"(d) : "l"(a), "l"(b));
    return d;
}

// =======================================================================
// 3xTF32 tensor-core GEMM core: C[m][n] = sum_k X[m][k] * W[n][k]  (X @ W^T)
// M=16384, N=1024, K=1024.
// Block tile 128x128, BK=8, 256 threads = 8 warps (4m x 2n), warp tile 32x64.
// 2 CTAs/SM (launch_bounds(256,2)) to double issue-slot utilization —
// R7 ncu showed occ=12.4%, issue=40.9%, tensor=40.3% (issue-starved).
// hi/lo split done ONCE at smem staging; smem holds float2{hi,lo} (LDS.64).
// XOR swizzle p = col ^ (((row>>2)&1)<<3): conflict-free for BK=8 staging
// stores (rows 0-3 vs 4-7 bank sets disjoint per 16-lane phase) AND frag loads.
// mma.sync.m16n8k8.tf32: acc += Ahi*Bhi + Ahi*Blo + Alo*Bhi.
// =======================================================================
__device__ __forceinline__ uint32_t f32_to_tf32(float x) {
    uint32_t r;
    asm("cvt.rna.tf32.f32 %0, %1;" : "=r"(r) : "f"(x));
    return r;
}
__device__ __forceinline__ float2 split_tf32(float x) {
    uint32_t hb = f32_to_tf32(x);
    float h = __uint_as_float(hb);
    uint32_t lb = f32_to_tf32(x - h);
    return make_float2(h, __uint_as_float(lb));
}
__device__ __forceinline__ void mma_tf32(float c[4], const uint32_t a[4],
                                         uint32_t b0, uint32_t b1) {
    asm volatile(
        "mma.sync.aligned.m16n8k8.row.col.f32.tf32.tf32.f32 "
        "{%0,%1,%2,%3}, {%4,%5,%6,%7}, {%8,%9}, {%0,%1,%2,%3};"
        : "+f"(c[0]), "+f"(c[1]), "+f"(c[2]), "+f"(c[3])
        : "r"(a[0]), "r"(a[1]), "r"(a[2]), "r"(a[3]), "r"(b0), "r"(b1));
}

#define LD2 132   // float2 row stride (8 banks/row)
#define SWZ(row, col) ((col) ^ ((((row) >> 2) & 1) << 3))

struct GemmCtx {
    int tid, lane, warp, gid, tig, wm, wn, bm, bn;
};

__device__ __forceinline__ void gemm_mainloop(
    const float* __restrict__ X, const float* __restrict__ W,
    const GemmCtx& g, float c[2][8][4],
    float2 (*As2)[LD2], float2 (*Bs2)[LD2])
{
    #pragma unroll
    for (int mt = 0; mt < 2; mt++)
        #pragma unroll
        for (int nt = 0; nt < 8; nt++)
            #pragma unroll
            for (int r = 0; r < 4; r++) c[mt][nt][r] = 0.f;

    const int ml = g.tid >> 1;          // 0..127
    const int kl = (g.tid & 1) << 2;    // 0 or 4

    const float* Xr = &X[(size_t)(g.bm + ml) * HID_ + kl];
    const float* Wr = &W[(size_t)(g.bn + ml) * HID_ + kl];

    float4 ra = *(const float4*)&Xr[0];
    float4 rb = *(const float4*)&Wr[0];

    for (int k0 = 0; k0 < HID_; k0 += 8) {
        As2[kl + 0][SWZ(kl + 0, ml)] = split_tf32(ra.x);
        As2[kl + 1][SWZ(kl + 1, ml)] = split_tf32(ra.y);
        As2[kl + 2][SWZ(kl + 2, ml)] = split_tf32(ra.z);
        As2[kl + 3][SWZ(kl + 3, ml)] = split_tf32(ra.w);
        Bs2[kl + 0][SWZ(kl + 0, ml)] = split_tf32(rb.x);
        Bs2[kl + 1][SWZ(kl + 1, ml)] = split_tf32(rb.y);
        Bs2[kl + 2][SWZ(kl + 2, ml)] = split_tf32(rb.z);
        Bs2[kl + 3][SWZ(kl + 3, ml)] = split_tf32(rb.w);
        __syncthreads();

        if (k0 + 8 < HID_) {
            ra = *(const float4*)&Xr[k0 + 8];
            rb = *(const float4*)&Wr[k0 + 8];
        }

        uint32_t ah[2][4], al[2][4];
        #pragma unroll
        for (int mt = 0; mt < 2; mt++) {
            int m0 = g.wm * 32 + mt * 16;
            float2 v0 = As2[g.tig    ][SWZ(g.tig,     m0 + g.gid)];
            float2 v1 = As2[g.tig    ][SWZ(g.tig,     m0 + g.gid + 8)];
            float2 v2 = As2[g.tig + 4][SWZ(g.tig + 4, m0 + g.gid)];
            float2 v3 = As2[g.tig + 4][SWZ(g.tig + 4, m0 + g.gid + 8)];
            ah[mt][0] = __float_as_uint(v0.x); al[mt][0] = __float_as_uint(v0.y);
            ah[mt][1] = __float_as_uint(v1.x); al[mt][1] = __float_as_uint(v1.y);
            ah[mt][2] = __float_as_uint(v2.x); al[mt][2] = __float_as_uint(v2.y);
            ah[mt][3] = __float_as_uint(v3.x); al[mt][3] = __float_as_uint(v3.y);
        }
        #pragma unroll
        for (int nt = 0; nt < 8; nt++) {
            int n0 = g.wn * 64 + nt * 8;
            float2 w0 = Bs2[g.tig    ][SWZ(g.tig,     n0 + g.gid)];
            float2 w1 = Bs2[g.tig + 4][SWZ(g.tig + 4, n0 + g.gid)];
            uint32_t bh0 = __float_as_uint(w0.x), bl0 = __float_as_uint(w0.y);
            uint32_t bh1 = __float_as_uint(w1.x), bl1 = __float_as_uint(w1.y);
            #pragma unroll
            for (int mt = 0; mt < 2; mt++) {
                mma_tf32(c[mt][nt], ah[mt], bh0, bh1);
                mma_tf32(c[mt][nt], ah[mt], bl0, bl1);
                mma_tf32(c[mt][nt], al[mt], bh0, bh1);
            }
        }
        __syncthreads();
    }
}

__device__ __forceinline__ GemmCtx make_ctx(int bx, int by) {
    GemmCtx g;
    g.tid  = threadIdx.x;
    g.lane = g.tid & 31;
    g.warp = g.tid >> 5;
    g.gid  = g.lane >> 2;
    g.tig  = g.lane & 3;
    g.wm   = g.warp & 3;
    g.wn   = g.warp >> 2;
    g.bm   = by * 128;
    g.bn   = bx * 128;
    return g;
}

// ---- fused QKV projection: blockIdx.z selects {q(+rope), k(+rope), v} ----
__global__ __launch_bounds__(256, 2)
void tgemm_qkv(const float* __restrict__ X,
               const float* __restrict__ Wq, const float* __restrict__ Wk,
               const float* __restrict__ Wv,
               const float* __restrict__ cosT, const float* __restrict__ sinT)
{
    __shared__ __align__(16) float2 As2[8][LD2];
    __shared__ __align__(16) float2 Bs2[8][LD2];
    GemmCtx g = make_ctx(blockIdx.x, blockIdx.y);
    const int bz = blockIdx.z;
    const float* W = (bz == 0) ? Wq : (bz == 1) ? Wk : Wv;
    float* Cout    = (bz == 0) ? g_q : (bz == 1) ? g_k : g_v;

    float c[2][8][4];
    gemm_mainloop(X, W, g, c, As2, Bs2);

    int h = (g.bn + g.wn * 64) >> 6;
    if (bz < 2) {
        // scatter into (B,H,S,D) with fused RoPE; thread holds (dd, dd+32) as (nt, nt+4)
        #pragma unroll
        for (int mt = 0; mt < 2; mt++) {
            #pragma unroll
            for (int half = 0; half < 2; half++) {
                int m  = g.bm + g.wm * 32 + mt * 16 + g.gid + half * 8;
                int b_ = m / S_, s_ = m % S_;
                const float* cr = cosT + (size_t)s_ * D_;
                const float* sr = sinT + (size_t)s_ * D_;
                float* dst = &Cout[(((size_t)(b_ * NH_ + h)) * S_ + s_) * D_];
                #pragma unroll
                for (int nt = 0; nt < 4; nt++) {
                    int dd = nt * 8 + 2 * g.tig;
                    float o1[2], o2[2];
                    #pragma unroll
                    for (int j = 0; j < 2; j++) {
                        float x1 = c[mt][nt    ][half * 2 + j];
                        float x2 = c[mt][nt + 4][half * 2 + j];
                        o1[j] = x1 * cr[dd + j]      - x2 * sr[dd + j];
                        o2[j] = x2 * cr[dd + 32 + j] + x1 * sr[dd + 32 + j];
                    }
                    *(float2*)&dst[dd]      = make_float2(o1[0], o1[1]);
                    *(float2*)&dst[dd + 32] = make_float2(o2[0], o2[1]);
                }
            }
        }
    } else {
        // plain scatter into (B,H,S,D)
        #pragma unroll
        for (int mt = 0; mt < 2; mt++) {
            #pragma unroll
            for (int nt = 0; nt < 8; nt++) {
                int dd = nt * 8 + 2 * g.tig;
                #pragma unroll
                for (int half = 0; half < 2; half++) {
                    int m  = g.bm + g.wm * 32 + mt * 16 + g.gid + half * 8;
                    int b_ = m / S_, s_ = m % S_;
                    *(float2*)&Cout[(((size_t)(b_ * NH_ + h)) * S_ + s_) * D_ + dd] =
                        make_float2(c[mt][nt][half * 2], c[mt][nt][half * 2 + 1]);
                }
            }
        }
    }
}

// ---- output projection: row-major result into d_out ----
__global__ __launch_bounds__(256, 2)
void tgemm_out(const float* __restrict__ X, const float* __restrict__ W,
               float* __restrict__ Cout)
{
    __shared__ __align__(16) float2 As2[8][LD2];
    __shared__ __align__(16) float2 Bs2[8][LD2];
    GemmCtx g = make_ctx(blockIdx.x, blockIdx.y);

    float c[2][8][4];
    gemm_mainloop(X, W, g, c, As2, Bs2);

    #pragma unroll
    for (int mt = 0; mt < 2; mt++) {
        #pragma unroll
        for (int nt = 0; nt < 8; nt++) {
            int n0 = g.bn + g.wn * 64 + nt * 8 + 2 * g.tig;
            #pragma unroll
            for (int half = 0; half < 2; half++) {
                int m = g.bm + g.wm * 32 + mt * 16 + g.gid + half * 8;
                *(float2*)&Cout[(size_t)m * HID_ + n0] =
                    make_float2(c[mt][nt][half * 2], c[mt][nt][half * 2 + 1]);
            }
        }
    }
}

// =======================================================================
// RFA chunk summaries: block per (b,h,c), 128 threads (one per key in chunk).
// =======================================================================
__global__ __launch_bounds__(128)
void rfa_kernel(const float* __restrict__ mu, const float* __restrict__ phi)
{
    int bid = blockIdx.x;          // B*NH*NC
    int c  = bid % NC_;
    int bh = bid / NC_;
    int h  = bh % NH_;
    const float* kc = g_k + ((size_t)bh * S_ + (size_t)c * CHUNK_) * D_;
    const float* vc = g_v + ((size_t)bh * S_ + (size_t)c * CHUNK_) * D_;

    __shared__ float sb[CHUNK_], sg[CHUNK_];
    int j = threadIdx.x;

    float dm = 0.f, dp = 0.f, nn = 0.f;
    const float4* krow = (const float4*)(kc + (size_t)j * D_);
    const float4* mu4  = (const float4*)(mu + h * D_);
    const float4* ph4  = (const float4*)(phi + h * D_);
    #pragma unroll
    for (int d4 = 0; d4 < 16; d4++) {
        float4 kv = krow[d4], m4 = mu4[d4], p4 = ph4[d4];
        dm += kv.x * m4.x + kv.y * m4.y + kv.z * m4.z + kv.w * m4.w;
        dp += kv.x * p4.x + kv.y * p4.y + kv.z * p4.z + kv.w * p4.w;
        nn += kv.x * kv.x + kv.y * kv.y + kv.z * kv.z + kv.w * kv.w;
    }
    float lb = SCALE_ * dm - SCALE_ * 0.5f * nn;
    float lg = SCALE_ * dp - SCALE_ * 0.5f * nn;
    sb[j] = lb; sg[j] = lg;
    __syncthreads();

    float mb = -INFINITY, mg = -INFINITY;
    for (int t = 0; t < CHUNK_; t++) { mb = fmaxf(mb, sb[t]); mg = fmaxf(mg, sg[t]); }
    float eb = __expf(lb - mb), eg = __expf(lg - mg);
    __syncthreads();
    sb[j] = eb; sg[j] = eg;
    __syncthreads();
    float ssb = 0.f, ssg = 0.f;
    for (int t = 0; t < CHUNK_; t++) { ssb += sb[t]; ssg += sg[t]; }
    float beta  = eb / ssb;
    float gamma = eg / ssg;
    __syncthreads();
    sb[j] = beta; sg[j] = gamma;
    __syncthreads();

    if (threadIdx.x < 64) {
        int d = threadIdx.x;
        float a = 0.f;
        for (int t = 0; t < CHUNK_; t++) a += sb[t] * kc[(size_t)t * D_ + d];
        g_rfa_k[((size_t)bh * NC_ + c) * D_ + d] = a;
    } else {
        int d = threadIdx.x - 64;
        float a = 0.f;
        for (int t = 0; t < CHUNK_; t++) a += sg[t] * vc[(size_t)t * D_ + d];
        g_rfa_v[((size_t)bh * NC_ + c) * D_ + d] = a;
    }
}

// =======================================================================
// Attention: block = (b,h,w, query-tile of 128). One query row per thread,
// streaming softmax over (causal window keys) ++ (allowed RFA chunks).
// Inner loops use packed fp32x2 (FFMA2) — 2 fp32 FMA per instruction.
// =======================================================================
__global__ __launch_bounds__(128, 2)
void attn_kernel()
{
    int bid = blockIdx.x;               // B*NH*NW*4
    int qt = bid & 3;
    int w  = (bid >> 2) & 7;
    int bh = bid >> 5;                  // b*NH + h
    int h  = bh % NH_;
    int b_ = bh / NH_;

    const float* qbase = g_q + ((size_t)bh * S_ + (size_t)w * WIN_ + (size_t)qt * 128) * D_;
    const float* kbase = g_k + ((size_t)bh * S_ + (size_t)w * WIN_) * D_;
    const float* vbase = g_v + ((size_t)bh * S_ + (size_t)w * WIN_) * D_;

    const int tid = threadIdx.x;

    // load q, fold scale, pack into fp32x2 pairs
    unsigned long long q2[32];
    {
        const float4* qr = (const float4*)(qbase + (size_t)tid * D_);
        #pragma unroll
        for (int i = 0; i < 16; i++) {
            float4 v = qr[i];
            q2[2*i]   = pack2(v.x * SCALE_, v.y * SCALE_);
            q2[2*i+1] = pack2(v.z * SCALE_, v.w * SCALE_);
        }
    }
    unsigned long long acc2[32];
    #pragma unroll
    for (int i = 0; i < 32; i++) acc2[i] = 0ULL;   // {0.0f, 0.0f}
    float m = -INFINITY, l = 0.f;

    __shared__ __align__(16) float ks[64][D_];
    __shared__ __align__(16) float vs[64][D_];

    const int jmax_local = qt * 128 + tid;       // inclusive causal limit
    const int ntiles = qt * 2 + 2;

    for (int t = 0; t < ntiles; t++) {
        __syncthreads();
        #pragma unroll
        for (int i = 0; i < 8; i++) {
            int f = tid + i * 128;
            int row = f >> 4, col = (f & 15) << 2;
            *(float4*)&ks[row][col] = *(const float4*)&kbase[(size_t)(t * 64 + row) * D_ + col];
            *(float4*)&vs[row][col] = *(const float4*)&vbase[(size_t)(t * 64 + row) * D_ + col];
        }
        __syncthreads();

        int jend = jmax_local - t * 64 + 1;
        if (jend > 64) jend = 64;
        for (int jj = 0; jj < jend; jj++) {
            const ulonglong2* kr = (const ulonglong2*)ks[jj];
            unsigned long long s0 = 0ULL, s1 = 0ULL, s2 = 0ULL, s3 = 0ULL;
            #pragma unroll
            for (int i = 0; i < 8; i++) {
                ulonglong2 ka = kr[2*i];
                ulonglong2 kb = kr[2*i+1];
                s0 = fma2(q2[4*i],   ka.x, s0);
                s1 = fma2(q2[4*i+1], ka.y, s1);
                s2 = fma2(q2[4*i+2], kb.x, s2);
                s3 = fma2(q2[4*i+3], kb.y, s3);
            }
            s0 = add2(s0, s1);
            s2 = add2(s2, s3);
            s0 = add2(s0, s2);
            float slo, shi;
            unpack2(s0, slo, shi);
            float s = slo + shi;

            if (s > m) {
                float corr = __expf(m - s);
                unsigned long long c2 = pack2(corr, corr);
                #pragma unroll
                for (int i = 0; i < 32; i++) acc2[i] = mul2(acc2[i], c2);
                l *= corr;
                m = s;
            }
            float p = __expf(s - m);
            l += p;
            unsigned long long p2 = pack2(p, p);
            const ulonglong2* vr = (const ulonglong2*)vs[jj];
            #pragma unroll
            for (int i = 0; i < 16; i++) {
                ulonglong2 vv = vr[i];
                acc2[2*i]   = fma2(p2, vv.x, acc2[2*i]);
                acc2[2*i+1] = fma2(p2, vv.y, acc2[2*i+1]);
            }
        }
    }

    // ---- chunk-RFA part: chunks c < w*CPW ----
    const int ncn = w * CPW_;
    __syncthreads();
    for (int f = tid; f < ncn * 16; f += 128) {
        int row = f >> 4, col = (f & 15) << 2;
        *(float4*)&ks[row][col] = *(const float4*)&g_rfa_k[((size_t)bh * NC_ + row) * D_ + col];
        *(float4*)&vs[row][col] = *(const float4*)&g_rfa_v[((size_t)bh * NC_ + row) * D_ + col];
    }
    __syncthreads();
    for (int c = 0; c < ncn; c++) {
        const ulonglong2* kr = (const ulonglong2*)ks[c];
        unsigned long long s0 = 0ULL, s1 = 0ULL, s2 = 0ULL, s3 = 0ULL;
        #pragma unroll
        for (int i = 0; i < 8; i++) {
            ulonglong2 ka = kr[2*i];
            ulonglong2 kb = kr[2*i+1];
            s0 = fma2(q2[4*i],   ka.x, s0);
            s1 = fma2(q2[4*i+1], ka.y, s1);
            s2 = fma2(q2[4*i+2], kb.x, s2);
            s3 = fma2(q2[4*i+3], kb.y, s3);
        }
        s0 = add2(s0, s1);
        s2 = add2(s2, s3);
        s0 = add2(s0, s2);
        float slo, shi;
        unpack2(s0, slo, shi);
        float s = slo + shi;

        if (s > m) {
            float corr = __expf(m - s);
            unsigned long long c2 = pack2(corr, corr);
            #pragma unroll
            for (int i = 0; i < 32; i++) acc2[i] = mul2(acc2[i], c2);
            l *= corr;
            m = s;
        }
        float p = __expf(s - m);
        l += p;
        unsigned long long p2 = pack2(p, p);
        const ulonglong2* vr = (const ulonglong2*)vs[c];
        #pragma unroll
        for (int i = 0; i < 16; i++) {
            ulonglong2 vv = vr[i];
            acc2[2*i]   = fma2(p2, vv.x, acc2[2*i]);
            acc2[2*i+1] = fma2(p2, vv.y, acc2[2*i+1]);
        }
    }

    float inv = 1.0f / l;
    unsigned long long inv2 = pack2(inv, inv);
    int sg_ = w * WIN_ + qt * 128 + tid;
    float* out = g_att + ((size_t)b_ * S_ + sg_) * HID_ + (size_t)h * D_;
    #pragma unroll
    for (int i = 0; i < 16; i++) {
        unsigned long long t0 = mul2(acc2[2*i],   inv2);
        unsigned long long t1 = mul2(acc2[2*i+1], inv2);
        float a, b, cc, d;
        unpack2(t0, a, b);
        unpack2(t1, cc, d);
        *(float4*)&out[i * 4] = make_float4(a, b, cc, d);
    }
}

// =======================================================================
// launch
// =======================================================================
extern "C" void kernel_launch(void* const* d_in, const int* in_sizes, int n_in,
                              void* d_out, int out_size)
{
    const float* X    = (const float*)d_in[0];   // hidden_states (B,S,HID)
    const float* Wq   = (const float*)d_in[1];
    const float* Wk   = (const float*)d_in[2];
    const float* Wv   = (const float*)d_in[3];
    const float* Wo   = (const float*)d_in[4];
    const float* mu   = (const float*)d_in[5];   // (1,NH,1,1,D)
    const float* phi  = (const float*)d_in[6];
    const float* cosT = (const float*)d_in[7];   // (1,1,S,D)
    const float* sinT = (const float*)d_in[8];
    float* out = (float*)d_out;

    float* att_p;
    cudaGetSymbolAddress((void**)&att_p, g_att);

    // fused q/k/v projections (+RoPE for q,k) -> (B,H,S,D)
    dim3 qkv_grid(HID_ / 128, M_TOT / 128, 3);   // (8, 128, 3)
    tgemm_qkv<<<qkv_grid, 256>>>(X, Wq, Wk, Wv, cosT, sinT);

    // RFA chunk summaries
    rfa_kernel<<<B_ * NH_ * NC_, 128>>>(mu, phi);

    // attention
    attn_kernel<<<B_ * NH_ * NW_ * 4, 128>>>();

    // output projection -> d_out
    dim3 ogrid(HID_ / 128, M_TOT / 128);         // (8, 128)
    tgemm_out<<<ogrid, 256>>>(att_p, Wo, out);
}